// round 16
// baseline (speedup 1.0000x reference)
#include <cuda_runtime.h>
#include <math.h>

#define Bn 4
#define Tt 8
#define Cc 64
#define Ff 16
#define Nn 8192
#define HW 1024      // H*W
#define BN (Bn*Nn)   // 32768

// gemv config
#define GBLK 148          // persistent blocks (1/SM)
#define GTHR 512          // 16 warps
#define NWARPS (GBLK*16)  // 2368
#define NTILE 4096        // 2 rows per tile
#define STAGES 3
#define NCHUNK 64         // 64 chunks x 512B per row
#define WROW_BYTES 32768  // 8192 floats
// smem: pooled 4*2048 float4 = 128KB ; W stages 16 warps*3*2*512B = 48KB
#define SM_POOL_BYTES 131072
#define SM_W_BYTES    49152
#define SM_TOTAL      (SM_POOL_BYTES + SM_W_BYTES)

typedef unsigned long long u64;

__device__ __align__(16) float g_pooled[BN];
__device__ __align__(16) float g_v[BN];
__device__ int g_ctr;

// ---- packed f32x2 helpers ----
__device__ __forceinline__ u64 f2fma(u64 a, u64 b, u64 c) {
    u64 d;
    asm("fma.rn.f32x2 %0, %1, %2, %3;" : "=l"(d) : "l"(a), "l"(b), "l"(c));
    return d;
}
__device__ __forceinline__ u64 f2add(u64 a, u64 b) {
    u64 d;
    asm("add.rn.f32x2 %0, %1, %2;" : "=l"(d) : "l"(a), "l"(b));
    return d;
}
__device__ __forceinline__ u64 f2mul(u64 a, u64 b) {
    u64 d;
    asm("mul.rn.f32x2 %0, %1, %2;" : "=l"(d) : "l"(a), "l"(b));
    return d;
}
__device__ __forceinline__ u64 f2pack(float lo, float hi) {
    u64 d;
    asm("mov.b64 %0, {%1, %2};" : "=l"(d) : "f"(lo), "f"(hi));
    return d;
}
__device__ __forceinline__ void f2unpack(u64 a, float& lo, float& hi) {
    asm("mov.b64 {%0, %1}, %2;" : "=f"(lo), "=f"(hi) : "l"(a));
}
__device__ __forceinline__ u64 ld64(const float* p) {
    return __double_as_longlong(*reinterpret_cast<const double*>(p));
}
__device__ __forceinline__ void cpasync16(unsigned dst, const void* src) {
    asm volatile("cp.async.cg.shared.global [%0], [%1], 16;" :: "r"(dst), "l"(src));
}
#define CP_COMMIT() asm volatile("cp.async.commit_group;" ::: "memory")
#define CP_WAIT(n)  asm volatile("cp.async.wait_group %0;" :: "n"(n) : "memory")
#define PREFETCH_L2(p) asm volatile("prefetch.global.L2 [%0];" :: "l"(p))

// ---------------------------------------------------------------------------
// Kernel 1: pooled[b,n] = wbar . x[b,:,n] + bbar   (conv1+avgpool collapsed)
// Coalesced float2 layout; L2-prefetch all 64 channel lines up front.
// Also presets the gemv tile-steal counter.
// ---------------------------------------------------------------------------
__global__ void __launch_bounds__(128, 1) pooled_kernel(
    const float* __restrict__ x,
    const float* __restrict__ conv1_w,
    const float* __restrict__ conv1_b)
{
    __shared__ float swb[Cc];
    __shared__ float sbb;
    int tid = threadIdx.x;
    if (blockIdx.x == 0 && tid == 0) g_ctr = NWARPS;   // steal counter for gemv

    int i = blockIdx.x * 128 + tid;    // [0, 16384) = BN/2
    int bb = i >> 12;                  // 4096 float2 per batch
    int j  = i & 4095;
    int t  = j >> 9;                   // 512 float2 per t
    int p  = j & 511;
    const float* xp = x + (size_t)((bb * Tt + t) * Cc) * HW + p * 2;

    // One prefetch per 128B line (16 threads share a line)
    if ((p & 15) == 0) {
        #pragma unroll
        for (int c = 0; c < Cc; ++c) PREFETCH_L2(xp + c * HW);
    }

    if (tid < Cc) {
        float s = 0.f;
        #pragma unroll
        for (int f = 0; f < Ff; ++f) s += conv1_w[f * Cc + tid];
        swb[tid] = s * (1.f / Ff);
    }
    if (tid == Cc) {
        float s = 0.f;
        #pragma unroll
        for (int f = 0; f < Ff; ++f) s += conv1_b[f];
        sbb = s * (1.f / Ff);
    }
    __syncthreads();

    float ax = 0.f, ay = 0.f;
    #pragma unroll
    for (int cb = 0; cb < Cc; cb += 16) {
        u64 xv[16];
        #pragma unroll
        for (int k = 0; k < 16; ++k) xv[k] = ld64(xp + (cb + k) * HW);
        #pragma unroll
        for (int k = 0; k < 16; ++k) {
            float lo, hi;
            f2unpack(xv[k], lo, hi);
            float w = swb[cb + k];
            ax = fmaf(w, lo, ax);
            ay = fmaf(w, hi, ay);
        }
    }
    *reinterpret_cast<float2*>(&g_pooled[bb * Nn + t * HW + p * 2]) =
        make_float2(ax + sbb, ay + sbb);
}

// ---------------------------------------------------------------------------
// Kernel 2: v[b,n] = sigmoid(pooled[b,:] . W[n,:] + bias[n])
// Persistent 148 blocks x 512 thr. Full pooled in smem (read-only after one
// barrier). Per-warp cp.async 3-stage W pipeline. Warp = 2 rows, chunk =
// 512B per row (32 lanes x 16B). Tile steal for tail balance.
// ---------------------------------------------------------------------------
__global__ void __launch_bounds__(GTHR, 1) gemv_kernel(
    const float* __restrict__ Wm,
    const float* __restrict__ bias)
{
    extern __shared__ __align__(16) char smem_raw[];
    float4* s_pool = reinterpret_cast<float4*>(smem_raw);           // [b*2048+k4]
    char*   s_w    = smem_raw + SM_POOL_BYTES;

    int tid  = threadIdx.x;
    int warp = tid >> 5;
    int lane = tid & 31;

    // stage pooled once
    const float4* Pg = (const float4*)g_pooled;
    #pragma unroll
    for (int i = 0; i < 16; ++i)
        s_pool[tid + i * GTHR] = __ldg(Pg + tid + i * GTHR);
    __syncthreads();

    unsigned wsbase = (unsigned)__cvta_generic_to_shared(s_w)
                    + warp * (STAGES * 2 * 512) + lane * 16;

    int tile = blockIdx.x * 16 + warp;   // static first tile (< NWARPS < NTILE)
    while (tile < NTILE) {
        const char* wrow = (const char*)Wm + (size_t)tile * (2 * WROW_BYTES) + lane * 16;

        // prime 3 stages (chunks 0..2); chunk stride = 512B per row
        #pragma unroll
        for (int s = 0; s < STAGES; ++s) {
            cpasync16(wsbase + s * 1024,       wrow + s * 512);
            cpasync16(wsbase + s * 1024 + 512, wrow + WROW_BYTES + s * 512);
            CP_COMMIT();
        }

        u64 acc[Bn][2];
        #pragma unroll
        for (int b = 0; b < Bn; ++b) { acc[b][0] = 0ull; acc[b][1] = 0ull; }

        #pragma unroll 1
        for (int c = 0; c < NCHUNK; ++c) {
            CP_WAIT(2);                         // chunk c landed
            int st = c - (c / 3) * 3;           // c % 3
            unsigned a = wsbase + st * 1024;
            u64 w0lo, w0hi, w1lo, w1hi;
            asm volatile("ld.shared.v2.u64 {%0,%1}, [%2];"
                         : "=l"(w0lo), "=l"(w0hi) : "r"(a));
            asm volatile("ld.shared.v2.u64 {%0,%1}, [%2];"
                         : "=l"(w1lo), "=l"(w1hi) : "r"(a + 512));
            #pragma unroll
            for (int b = 0; b < Bn; ++b) {
                ulonglong2 p = *reinterpret_cast<const ulonglong2*>(
                    &s_pool[b * 2048 + c * 32 + lane]);
                acc[b][0] = f2fma(p.x, w0lo, acc[b][0]);
                acc[b][0] = f2fma(p.y, w0hi, acc[b][0]);
                acc[b][1] = f2fma(p.x, w1lo, acc[b][1]);
                acc[b][1] = f2fma(p.y, w1hi, acc[b][1]);
            }
            if (c + STAGES < NCHUNK) {          // refill freed stage
                cpasync16(a,       wrow + (c + STAGES) * 512);
                cpasync16(a + 512, wrow + WROW_BYTES + (c + STAGES) * 512);
            }
            CP_COMMIT();
        }
        CP_WAIT(0);

        // reduce + write 2 rows x 4 batches
        #pragma unroll
        for (int r = 0; r < 2; ++r) {
            #pragma unroll
            for (int b = 0; b < Bn; ++b) {
                float lo, hi;
                f2unpack(acc[b][r], lo, hi);
                float v = lo + hi;
                #pragma unroll
                for (int off = 16; off > 0; off >>= 1)
                    v += __shfl_xor_sync(0xffffffffu, v, off);
                if (lane == 0) {
                    int n = tile * 2 + r;
                    float s = v + bias[n];
                    g_v[b * Nn + n] = 1.f / (1.f + __expf(-s));
                }
            }
        }

        if (lane == 0) tile = atomicAdd(&g_ctr, 1);
        tile = __shfl_sync(0xffffffffu, tile, 0);
    }
}

// ---------------------------------------------------------------------------
// Kernel 3: out[b,t,f,h,w] = v[b,n] * (g3_w @ x + g3_b)[b,n,f]
// One thread = 2 hw; prefetch all 64 channel lines, then compute.
// ---------------------------------------------------------------------------
__global__ void __launch_bounds__(128, 1) out_kernel(
    const float* __restrict__ x,
    const float* __restrict__ g3_w,
    const float* __restrict__ g3_b,
    float* __restrict__ out)
{
    __shared__ u64 sw2[Ff * Cc];   // (w,w) packed, 8KB
    __shared__ u64 sb2[Ff];

    int tid = threadIdx.x;
    int i2  = blockIdx.x * 128 + tid;   // [0, BN/2)
    int b   = i2 >> 12;
    int j   = i2 & 4095;
    int t   = j >> 9;
    int p   = j & 511;
    const float* xp = x + (size_t)((b * Tt + t) * Cc) * HW + p * 2;

    if ((p & 15) == 0) {
        #pragma unroll
        for (int c = 0; c < Cc; ++c) PREFETCH_L2(xp + c * HW);
    }

    for (int i = tid; i < Ff * Cc; i += 128) {
        float w = g3_w[i];
        sw2[i] = f2pack(w, w);
    }
    if (tid < Ff) {
        float bb = g3_b[tid];
        sb2[tid] = f2pack(bb, bb);
    }
    __syncthreads();

    u64 acc[Ff];
    #pragma unroll
    for (int f = 0; f < Ff; ++f) acc[f] = 0ull;

    #pragma unroll
    for (int cb = 0; cb < Cc; cb += 16) {
        u64 xv[16];
        #pragma unroll
        for (int i = 0; i < 16; ++i) xv[i] = ld64(xp + (cb + i) * HW);
        #pragma unroll
        for (int i = 0; i < 16; ++i)
            #pragma unroll
            for (int f = 0; f < Ff; ++f)
                acc[f] = f2fma(xv[i], sw2[f * Cc + cb + i], acc[f]);
    }

    u64 v2 = ld64(&g_v[b * Nn + t * HW + p * 2]);
    float* op = out + (size_t)((b * Tt + t) * Ff) * HW + p * 2;
    #pragma unroll
    for (int f = 0; f < Ff; ++f) {
        u64 r = f2mul(f2add(acc[f], sb2[f]), v2);
        float lo, hi;
        f2unpack(r, lo, hi);
        *reinterpret_cast<float2*>(op + f * HW) = make_float2(lo, hi);
    }
}

// ---------------------------------------------------------------------------
extern "C" void kernel_launch(void* const* d_in, const int* in_sizes, int n_in,
                              void* d_out, int out_size)
{
    const float* x       = (const float*)d_in[0];
    // d_in[1] = x1 (unused by reference)
    const float* conv1_w = (const float*)d_in[2];
    const float* conv1_b = (const float*)d_in[3];
    const float* g3_w    = (const float*)d_in[4];
    const float* g3_b    = (const float*)d_in[5];
    const float* ffnn1_w = (const float*)d_in[6];
    const float* ffnn1_b = (const float*)d_in[7];
    float* out = (float*)d_out;

    cudaFuncSetAttribute(gemv_kernel,
                         cudaFuncAttributeMaxDynamicSharedMemorySize, SM_TOTAL);

    pooled_kernel<<<BN / 2 / 128, 128>>>(x, conv1_w, conv1_b);
    gemv_kernel<<<GBLK, GTHR, SM_TOTAL>>>(ffnn1_w, ffnn1_b);
    out_kernel<<<BN / 2 / 128, 128>>>(x, g3_w, g3_b, out);
}